// round 3
// baseline (speedup 1.0000x reference)
#include <cuda_runtime.h>
#include <math.h>

// Problem shape (fixed by dataset): N=100000, H=32, K=15, C_in=C_out=64
#define MAXN 100000
#define NB_H 32
#define KPTS 15
#define CH   64

// Scratch (__device__ globals: allocation-free rule)
__device__ float4 g_pts4[MAXN];        // s_pts packed (w unused)
__device__ float  g_val[MAXN * CH];    // raw kpconv rows (active points only)
__device__ int    g_flag[MAXN];        // dedup flag
__device__ int    g_list[MAXN];        // active point list
__device__ int    g_cnt;
__device__ int    g_done;              // heavy-kernel block completion counter
__device__ float  g_sum[CH], g_sumsq[CH];
__device__ float  g_mean[CH], g_inv[CH], g_z[CH];

static __host__ __device__ __forceinline__ float kp_extent() {
    return (float)(0.1 * 1.2 / 2.5);
}

// Per-block candidate threshold^2 from kernel-point norms (cheap, L2-hit loads)
static __device__ __forceinline__ float candidate_thr2(const float* __restrict__ kp) {
    float mx = 0.0f;
#pragma unroll
    for (int k = 0; k < KPTS; k++) {
        const float a = __ldg(kp + 3*k), b = __ldg(kp + 3*k + 1), c = __ldg(kp + 3*k + 2);
        mx = fmaxf(mx, a*a + b*b + c*c);
    }
    const float t = (kp_extent() + sqrtf(mx)) * 1.0002f + 1e-6f;  // false positives ok
    return t * t;
}

// ---------------- init: pack s_pts into float4, zero state ----------------
__global__ void __launch_bounds__(256) init_kernel(const float* __restrict__ s_pts, int N)
{
    const int i = blockIdx.x * 256 + threadIdx.x;
    if (i == 0) { g_cnt = 0; g_done = 0; }
    if (i < CH) { g_sum[i] = 0.0f; g_sumsq[i] = 0.0f; }
    if (i < N) {
        g_flag[i] = 0;
        g_pts4[i] = make_float4(__ldg(s_pts + 3*i), __ldg(s_pts + 3*i + 1),
                                __ldg(s_pts + 3*i + 2), 0.0f);
    }
}

// ---------------- detect: 4 pairs/thread, float4 gathers, append active points ----------------
__global__ void __launch_bounds__(256) detect_kernel(
    const int* __restrict__ inds, const float* __restrict__ q_pts,
    const float* __restrict__ kp, int N)
{
    const float thr2 = candidate_thr2(kp);

    const int t = blockIdx.x * 256 + threadIdx.x;   // covers inds[4t .. 4t+3]
    const int n = t >> 3;                           // 8 threads per point
    if (n >= N) return;
    const int lane = threadIdx.x & 31;
    const unsigned FULL = 0xffffffffu;

    float qx = 0.f, qy = 0.f, qz = 0.f;
    if ((lane & 7) == 0) {
        qx = __ldg(q_pts + 3*n);
        qy = __ldg(q_pts + 3*n + 1);
        qz = __ldg(q_pts + 3*n + 2);
    }
    const int src = lane & ~7;
    qx = __shfl_sync(FULL, qx, src);
    qy = __shfl_sync(FULL, qy, src);
    qz = __shfl_sync(FULL, qz, src);

    const int4 iv = __ldg(reinterpret_cast<const int4*>(inds) + t);
    const int ids[4] = { iv.x, iv.y, iv.z, iv.w };

    bool any = false;
#pragma unroll
    for (int j = 0; j < 4; j++) {
        const int id = ids[j];
        if ((unsigned)id < (unsigned)N) {
            const float4 p = __ldg(&g_pts4[id]);
            const float dx = p.x - qx, dy = p.y - qy, dz = p.z - qz;
            const float r2 = fmaf(dx, dx, fmaf(dy, dy, dz * dz));
            any |= (r2 < thr2);
        }
    }
    if (any) {
        if (atomicCAS(&g_flag[n], 0, 1) == 0) {
            const int p = atomicAdd(&g_cnt, 1);
            g_list[p] = n;
        }
    }
}

// ---------------- heavy: exact KPConv for active points + fused stats finalize ----------------
#define HEAVY_BLOCKS 32
__global__ void __launch_bounds__(256) heavy_kernel(
    const int*   __restrict__ inds,
    const float* __restrict__ q_pts,
    const float* __restrict__ x,
    const float* __restrict__ kp,
    const float* __restrict__ W,   // [K, C, C]
    int N)
{
    __shared__ float sw[8][KPTS][CH];   // 30 KB
    const int warp = threadIdx.x >> 5;
    const int lane = threadIdx.x & 31;
    const unsigned FULL = 0xffffffffu;

    const int cnt = __ldg(&g_cnt);
    const float EXT  = kp_extent();
    const float EXT2 = EXT * EXT;
    const float INVE = 1.0f / EXT;
    const float thr2 = candidate_thr2(kp);

    float kx[KPTS], ky[KPTS], kz[KPTS];
#pragma unroll
    for (int k = 0; k < KPTS; k++) {
        kx[k] = __ldg(kp + 3*k);
        ky[k] = __ldg(kp + 3*k + 1);
        kz[k] = __ldg(kp + 3*k + 2);
    }

    for (int e = blockIdx.x * 8 + warp; e < cnt; e += HEAVY_BLOCKS * 8) {
        const int n = g_list[e];
        const float qx = __ldg(q_pts + 3*n);
        const float qy = __ldg(q_pts + 3*n + 1);
        const float qz = __ldg(q_pts + 3*n + 2);

        const int idx = __ldg(inds + n * NB_H + lane);
        const bool valid = ((unsigned)idx < (unsigned)N);
        float nx = 1e9f, ny = 1e9f, nz = 1e9f;
        if (valid) {
            const float4 p = __ldg(&g_pts4[idx]);
            nx = p.x - qx; ny = p.y - qy; nz = p.z - qz;
        }
        const float r2 = fmaf(nx, nx, fmaf(ny, ny, nz * nz));
        unsigned mask = __ballot_sync(FULL, valid && (r2 < thr2));

        float acc0[KPTS], acc1[KPTS];
#pragma unroll
        for (int k = 0; k < KPTS; k++) { acc0[k] = 0.0f; acc1[k] = 0.0f; }

        unsigned m = mask;
        while (m) {
            const int hs = __ffs(m) - 1;
            m &= (m - 1);
            const int   sidx = __shfl_sync(FULL, idx, hs);
            const float bx = __shfl_sync(FULL, nx, hs);
            const float by = __shfl_sync(FULL, ny, hs);
            const float bz = __shfl_sync(FULL, nz, hs);
            const float xv0 = __ldg(x + (long)sidx * CH + lane);
            const float xv1 = __ldg(x + (long)sidx * CH + lane + 32);
#pragma unroll
            for (int k = 0; k < KPTS; k++) {
                const float dx = bx - kx[k];
                const float dy = by - ky[k];
                const float dz = bz - kz[k];
                const float d2 = fmaf(dx, dx, fmaf(dy, dy, dz * dz));
                if (d2 < EXT2) {
                    const float w = fmaxf(1.0f - sqrtf(d2) * INVE, 0.0f);
                    acc0[k] = fmaf(w, xv0, acc0[k]);
                    acc1[k] = fmaf(w, xv1, acc1[k]);
                }
            }
        }

        unsigned kmask = 0;
#pragma unroll
        for (int k = 0; k < KPTS; k++) {
            sw[warp][k][lane]      = acc0[k];
            sw[warp][k][lane + 32] = acc1[k];
            if (__ballot_sync(FULL, (acc0[k] != 0.0f) || (acc1[k] != 0.0f)))
                kmask |= (1u << k);
        }
        __syncwarp();

        float o0 = 0.0f, o1 = 0.0f;
        for (int k = 0; k < KPTS; k++) {
            if (!(kmask & (1u << k))) continue;
            const float* Wk = W + (long)k * CH * CH;
#pragma unroll 8
            for (int c = 0; c < CH; c++) {
                const float wv = sw[warp][k][c];
                o0 = fmaf(wv, __ldg(Wk + c * CH + lane),      o0);
                o1 = fmaf(wv, __ldg(Wk + c * CH + lane + 32), o1);
            }
        }
        __syncwarp();

        g_val[(long)n * CH + lane]      = o0;
        g_val[(long)n * CH + lane + 32] = o1;
        atomicAdd(&g_sum[lane],        o0);
        atomicAdd(&g_sum[lane + 32],   o1);
        atomicAdd(&g_sumsq[lane],      o0 * o0);
        atomicAdd(&g_sumsq[lane + 32], o1 * o1);
    }

    // ---- fused finalize: last block computes mean / inv-std / normalized-zero ----
    __syncthreads();
    __shared__ int s_last;
    if (threadIdx.x == 0) {
        __threadfence();
        s_last = (atomicAdd(&g_done, 1) == HEAVY_BLOCKS - 1);
    }
    __syncthreads();
    if (s_last && threadIdx.x < CH) {
        const int t = threadIdx.x;
        const float invN = 1.0f / (float)N;
        const float mean = g_sum[t] * invN;
        const float var  = fmaxf(g_sumsq[t] * invN - mean * mean, 0.0f);
        const float inv  = rsqrtf(var + 1e-5f);
        const float z    = (0.0f - mean) * inv;
        g_mean[t] = mean;
        g_inv[t]  = inv;
        g_z[t]    = (z >= 0.0f) ? z : 0.1f * z;
    }
}

// ---------------- pass 3: pure constant stream-store ----------------
__global__ void __launch_bounds__(256) pass3_kernel(float4* __restrict__ out, int n4)
{
    __shared__ float4 cz[16];
    if (threadIdx.x < 16) {
        const int j = threadIdx.x * 4;
        cz[threadIdx.x] = make_float4(g_z[j], g_z[j+1], g_z[j+2], g_z[j+3]);
    }
    __syncthreads();
    const int base = blockIdx.x * (256 * 4) + threadIdx.x;
#pragma unroll
    for (int r = 0; r < 4; r++) {
        const int k = base + r * 256;
        if (k < n4) out[k] = cz[k & 15];
    }
}

// ---------------- fixup: overwrite active rows with normalized values ----------------
__global__ void __launch_bounds__(256) fixup_kernel(float* __restrict__ out)
{
    __shared__ float mm[CH], iv[CH];
    const int tid = threadIdx.x;
    if (tid < CH) { mm[tid] = g_mean[tid]; iv[tid] = g_inv[tid]; }
    __syncthreads();
    const int cnt = g_cnt;
    const int c = tid & 63;
    const int sub = tid >> 6;   // 4 rows in flight
    for (int e = sub; e < cnt; e += 4) {
        const int n = g_list[e];
        const float v = g_val[(long)n * CH + c];
        const float a = (v - mm[c]) * iv[c];
        out[(long)n * CH + c] = (a >= 0.0f) ? a : 0.1f * a;
    }
}

// ---------------- launch ----------------
extern "C" void kernel_launch(void* const* d_in, const int* in_sizes, int n_in,
                              void* d_out, int out_size) {
    const float* q_pts = (const float*)d_in[0];
    const float* s_pts = (const float*)d_in[1];
    const int*   inds  = (const int*)  d_in[2];
    const float* x     = (const float*)d_in[3];
    const float* kp    = (const float*)d_in[4];
    const float* W     = (const float*)d_in[5];
    float* out = (float*)d_out;

    const int N = in_sizes[0] / 3;

    init_kernel<<<(N + 255) / 256, 256>>>(s_pts, N);
    detect_kernel<<<(N * 8 + 255) / 256, 256>>>(inds, q_pts, kp, N);
    heavy_kernel<<<HEAVY_BLOCKS, 256>>>(inds, q_pts, x, kp, W, N);
    const int n4 = N * (CH / 4);
    pass3_kernel<<<(n4 + 1023) / 1024, 256>>>((float4*)out, n4);
    fixup_kernel<<<1, 256>>>(out);
}

// round 4
// speedup vs baseline: 1.4901x; 1.4901x over previous
#include <cuda_runtime.h>
#include <math.h>

// Problem shape (fixed by dataset): N=100000, H=32, K=15, C_in=C_out=64
#define MAXN 100000
#define NB_H 32
#define KPTS 15
#define CH   64

// Scratch (__device__ globals: allocation-free rule)
__device__ float4 g_pts4[MAXN];     // s_pts packed as float4 (w unused)
__device__ float  g_val[MAXN * CH]; // raw kpconv rows for active points
__device__ int    g_flag[MAXN];     // 1 if row active
__device__ float  g_sum[CH];
__device__ float  g_sumsq[CH];
__device__ float  g_thresh;         // squared candidate radius

static __host__ __device__ __forceinline__ float kp_extent() {
    return (float)(0.1 * 1.2 / 2.5);
}

// ---------------- init: pack s_pts, zero flags/sums, compute threshold ----------------
__global__ void __launch_bounds__(256) init_kernel(const float* __restrict__ s_pts,
                                                   const float* __restrict__ kp, int N)
{
    const int i = blockIdx.x * 256 + threadIdx.x;
    if (i < N) {
        g_flag[i] = 0;
        g_pts4[i] = make_float4(__ldg(s_pts + 3*i), __ldg(s_pts + 3*i + 1),
                                __ldg(s_pts + 3*i + 2), 0.0f);
    }
    if (i < CH) { g_sum[i] = 0.0f; g_sumsq[i] = 0.0f; }
    if (i == 0) {
        float mx = 0.0f;
        for (int k = 0; k < KPTS; k++) {
            const float a = kp[3*k], b = kp[3*k+1], c = kp[3*k+2];
            mx = fmaxf(mx, sqrtf(a*a + b*b + c*c));
        }
        const float t = (kp_extent() + mx) * 1.0002f + 1e-6f;  // false positives ok
        g_thresh = t * t;
    }
}

// ---------------- pass 1: one warp per point; float4 gather; inline heavy path ----------------
__global__ void __launch_bounds__(256) pass1_kernel(
    const float* __restrict__ q_pts,
    const int*   __restrict__ inds,
    const float* __restrict__ x,
    const float* __restrict__ kp,
    const float* __restrict__ W,   // [K, C, C]
    int N)
{
    __shared__ float sw[8][KPTS][CH];   // 30 KB

    const int warp = threadIdx.x >> 5;
    const int lane = threadIdx.x & 31;
    const int n = blockIdx.x * 8 + warp;
    if (n >= N) return;

    const float qx = __ldg(q_pts + 3*n);
    const float qy = __ldg(q_pts + 3*n + 1);
    const float qz = __ldg(q_pts + 3*n + 2);

    const int idx = __ldg(inds + n * NB_H + lane);
    const bool valid = ((unsigned)idx < (unsigned)N);
    float nx = 1e9f, ny = 1e9f, nz = 1e9f;
    if (valid) {
        const float4 p = __ldg(&g_pts4[idx]);   // single 16B gather (was 3 scalar gathers)
        nx = p.x - qx; ny = p.y - qy; nz = p.z - qz;
    }
    const float r2 = fmaf(nx, nx, fmaf(ny, ny, nz * nz));
    const float thr = g_thresh;

    const unsigned FULL = 0xffffffffu;
    unsigned mask = __ballot_sync(FULL, valid && (r2 < thr));
    if (mask == 0) return;   // ~99.9% of warps exit here

    // -------- heavy path (rare): exact reference math --------
    const float EXT  = kp_extent();
    const float EXT2 = EXT * EXT;
    const float INVE = 1.0f / EXT;

    float acc0[KPTS], acc1[KPTS];
#pragma unroll
    for (int k = 0; k < KPTS; k++) { acc0[k] = 0.0f; acc1[k] = 0.0f; }

    float kx[KPTS], ky[KPTS], kz[KPTS];
#pragma unroll
    for (int k = 0; k < KPTS; k++) {
        kx[k] = __ldg(kp + 3*k);
        ky[k] = __ldg(kp + 3*k + 1);
        kz[k] = __ldg(kp + 3*k + 2);
    }

    unsigned m = mask;
    while (m) {
        const int hs = __ffs(m) - 1;
        m &= (m - 1);
        const int   sidx = __shfl_sync(FULL, idx, hs);
        const float bx = __shfl_sync(FULL, nx, hs);
        const float by = __shfl_sync(FULL, ny, hs);
        const float bz = __shfl_sync(FULL, nz, hs);
        const float xv0 = __ldg(x + (long)sidx * CH + lane);
        const float xv1 = __ldg(x + (long)sidx * CH + lane + 32);
#pragma unroll
        for (int k = 0; k < KPTS; k++) {
            const float dx = bx - kx[k];
            const float dy = by - ky[k];
            const float dz = bz - kz[k];
            const float d2 = fmaf(dx, dx, fmaf(dy, dy, dz * dz));
            if (d2 < EXT2) {
                const float w = fmaxf(1.0f - sqrtf(d2) * INVE, 0.0f);
                acc0[k] = fmaf(w, xv0, acc0[k]);
                acc1[k] = fmaf(w, xv1, acc1[k]);
            }
        }
    }

    // stash weighted[k][c] in smem; track which k have any contribution
    unsigned kmask = 0;
#pragma unroll
    for (int k = 0; k < KPTS; k++) {
        sw[warp][k][lane]      = acc0[k];
        sw[warp][k][lane + 32] = acc1[k];
        if (__ballot_sync(FULL, (acc0[k] != 0.0f) || (acc1[k] != 0.0f)))
            kmask |= (1u << k);
    }
    __syncwarp();

    // out[d] = sum_{k,c} weighted[k,c] * W[k,c,d]; lane owns d=lane, d=lane+32
    float o0 = 0.0f, o1 = 0.0f;
    for (int k = 0; k < KPTS; k++) {
        if (!(kmask & (1u << k))) continue;
        const float* Wk = W + (long)k * CH * CH;
#pragma unroll 8
        for (int c = 0; c < CH; c++) {
            const float wv = sw[warp][k][c];
            o0 = fmaf(wv, __ldg(Wk + c * CH + lane),      o0);
            o1 = fmaf(wv, __ldg(Wk + c * CH + lane + 32), o1);
        }
    }

    g_val[(long)n * CH + lane]      = o0;
    g_val[(long)n * CH + lane + 32] = o1;
    if (lane == 0) g_flag[n] = 1;
    atomicAdd(&g_sum[lane],        o0);
    atomicAdd(&g_sum[lane + 32],   o1);
    atomicAdd(&g_sumsq[lane],      o0 * o0);
    atomicAdd(&g_sumsq[lane + 32], o1 * o1);
}

// ---------------- pass 3: per-block stats finalize + normalize/LeakyReLU stream ----------------
__global__ void __launch_bounds__(256) pass3_kernel(float* __restrict__ out, int N) {
    __shared__ float zz[CH], mm[CH], iv[CH];
    const int t = threadIdx.x;
    if (t < CH) {
        // recompute stats per block: 2 broadcast L2 loads + a few ALU ops (cheaper than a launch)
        const float invN = 1.0f / (float)N;
        const float mean = g_sum[t] * invN;
        const float var  = fmaxf(g_sumsq[t] * invN - mean * mean, 0.0f);
        const float inv  = rsqrtf(var + 1e-5f);
        const float z    = (0.0f - mean) * inv;
        mm[t] = mean;
        iv[t] = inv;
        zz[t] = (z >= 0.0f) ? z : 0.1f * z;
    }
    __syncthreads();

    const int r = blockIdx.x * 16 + (t >> 4);   // 16 rows per block
    if (r >= N) return;
    const int j = (t & 15) * 4;                 // 16 threads * float4 = 64 channels

    float4 o;
    if (__ldg(&g_flag[r])) {
        const float4 v = *reinterpret_cast<const float4*>(g_val + (long)r * CH + j);
        float a = (v.x - mm[j])     * iv[j];
        float b = (v.y - mm[j + 1]) * iv[j + 1];
        float c = (v.z - mm[j + 2]) * iv[j + 2];
        float d = (v.w - mm[j + 3]) * iv[j + 3];
        o.x = (a >= 0.0f) ? a : 0.1f * a;
        o.y = (b >= 0.0f) ? b : 0.1f * b;
        o.z = (c >= 0.0f) ? c : 0.1f * c;
        o.w = (d >= 0.0f) ? d : 0.1f * d;
    } else {
        o = make_float4(zz[j], zz[j + 1], zz[j + 2], zz[j + 3]);
    }
    reinterpret_cast<float4*>(out)[(long)r * (CH / 4) + (t & 15)] = o;
}

// ---------------- launch: 3 kernels ----------------
extern "C" void kernel_launch(void* const* d_in, const int* in_sizes, int n_in,
                              void* d_out, int out_size) {
    const float* q_pts = (const float*)d_in[0];
    const float* s_pts = (const float*)d_in[1];
    const int*   inds  = (const int*)  d_in[2];
    const float* x     = (const float*)d_in[3];
    const float* kp    = (const float*)d_in[4];
    const float* W     = (const float*)d_in[5];
    float* out = (float*)d_out;

    const int N = in_sizes[0] / 3;

    init_kernel<<<(N + 255) / 256, 256>>>(s_pts, kp, N);
    pass1_kernel<<<(N + 7) / 8, 256>>>(q_pts, inds, x, kp, W, N);
    pass3_kernel<<<(N + 15) / 16, 256>>>(out, N);
}